// round 2
// baseline (speedup 1.0000x reference)
#include <cuda_runtime.h>

// out = relu(gamma * (x @ W3^T) + x @ W4^T)
//     = relu(x @ (gamma*W3 + W4)^T)
// The reference's softmax is over a size-1 axis (== 1.0), so the attention
// block is an identity on the W3 branch; W1/W2 are dead inputs.

#define DICT 20
#define OUTC 200
#define TILE_ROWS 64
#define BLOCK_THREADS 800          // 100 column-pair threads x 8 row-lanes = 25 warps
#define ROWS_PER_THREAD 8
#define GRID_BLOCKS 2048

__device__ float g_Wc[OUTC * DICT];   // combined weight, built per launch

__global__ void prep_Wc(const float* __restrict__ W3,
                        const float* __restrict__ W4,
                        const float* __restrict__ gamma) {
    float g = gamma[0];
    for (int i = blockIdx.x * blockDim.x + threadIdx.x; i < OUTC * DICT;
         i += gridDim.x * blockDim.x) {
        g_Wc[i] = fmaf(g, W3[i], W4[i]);
    }
}

// ---- packed f32x2 helpers (sm_103a FFMA2 path, PTX-only) ----
__device__ __forceinline__ unsigned long long pack2(float lo, float hi) {
    unsigned long long r;
    asm("mov.b64 %0, {%1, %2};" : "=l"(r) : "f"(lo), "f"(hi));
    return r;
}
__device__ __forceinline__ unsigned long long fma2(unsigned long long a,
                                                   unsigned long long b,
                                                   unsigned long long c) {
    unsigned long long d;
    asm("fma.rn.f32x2 %0, %1, %2, %3;" : "=l"(d) : "l"(a), "l"(b), "l"(c));
    return d;
}
__device__ __forceinline__ unsigned long long add2(unsigned long long a,
                                                   unsigned long long b) {
    unsigned long long d;
    asm("add.rn.f32x2 %0, %1, %2;" : "=l"(d) : "l"(a), "l"(b));
    return d;
}
__device__ __forceinline__ float2 unpack2(unsigned long long v) {
    float2 f;
    asm("mov.b64 {%0, %1}, %2;" : "=f"(f.x), "=f"(f.y) : "l"(v));
    return f;
}

__global__ __launch_bounds__(BLOCK_THREADS, 1)
void gemm_relu(const float* __restrict__ x, float* __restrict__ out, int ntiles) {
    __shared__ __align__(16) float xs[TILE_ROWS * DICT];   // 5 KB

    const int tid = threadIdx.x;
    const int cx  = tid % 100;   // owns output columns 2*cx, 2*cx+1
    const int ty  = tid / 100;   // row lane 0..7

    // Load this thread's two weight rows once; they persist across all tiles.
    unsigned long long w0[10], w1[10];
    {
        const float4* p0 = reinterpret_cast<const float4*>(g_Wc + (2 * cx) * DICT);
        const float4* p1 = reinterpret_cast<const float4*>(g_Wc + (2 * cx + 1) * DICT);
        #pragma unroll
        for (int i = 0; i < 5; i++) {
            float4 a = p0[i];
            float4 b = p1[i];
            w0[2 * i]     = pack2(a.x, a.y);
            w0[2 * i + 1] = pack2(a.z, a.w);
            w1[2 * i]     = pack2(b.x, b.y);
            w1[2 * i + 1] = pack2(b.z, b.w);
        }
    }

    for (int tile = blockIdx.x; tile < ntiles; tile += gridDim.x) {
        __syncthreads();  // protect xs reuse across iterations
        // Stage 64 rows x 20 floats = 1280 floats, coalesced.
        const float2* xsrc =
            reinterpret_cast<const float2*>(x + (size_t)tile * TILE_ROWS * DICT);
        if (tid < (TILE_ROWS * DICT) / 2)
            reinterpret_cast<float2*>(xs)[tid] = xsrc[tid];
        __syncthreads();

        #pragma unroll
        for (int r = 0; r < ROWS_PER_THREAD; r++) {
            const int lrow = ty * ROWS_PER_THREAD + r;
            // 20 floats of this row as 10 packed f32x2 (broadcast LDS.128)
            const ulonglong2* xp =
                reinterpret_cast<const ulonglong2*>(xs + lrow * DICT);
            ulonglong2 xv[5];
            #pragma unroll
            for (int i = 0; i < 5; i++) xv[i] = xp[i];

            // 4 independent FFMA2 chains (2 per output column)
            unsigned long long a0 = 0ull, b0 = 0ull, a1 = 0ull, b1 = 0ull;
            #pragma unroll
            for (int i = 0; i < 5; i++) {
                a0 = fma2(xv[i].x, w0[2 * i],     a0);
                b0 = fma2(xv[i].y, w0[2 * i + 1], b0);
                a1 = fma2(xv[i].x, w1[2 * i],     a1);
                b1 = fma2(xv[i].y, w1[2 * i + 1], b1);
            }
            float2 s0 = unpack2(add2(a0, b0));
            float2 s1 = unpack2(add2(a1, b1));
            float c0 = fmaxf(s0.x + s0.y, 0.0f);
            float c1 = fmaxf(s1.x + s1.y, 0.0f);

            const size_t grow = (size_t)tile * TILE_ROWS + lrow;
            float2* orow = reinterpret_cast<float2*>(out + grow * OUTC);
            orow[cx] = make_float2(c0, c1);   // coalesced 8B store
        }
    }
}

extern "C" void kernel_launch(void* const* d_in, const int* in_sizes, int n_in,
                              void* d_out, int out_size) {
    const float* x     = (const float*)d_in[0];
    // d_in[1] = W1, d_in[2] = W2 : dead (softmax over size-1 axis == 1)
    const float* W3    = (const float*)d_in[3];
    const float* W4    = (const float*)d_in[4];
    const float* gamma = (const float*)d_in[5];
    float* out = (float*)d_out;

    const int B = in_sizes[0] / DICT;
    const int ntiles = B / TILE_ROWS;   // B = 262144 -> 4096 tiles

    prep_Wc<<<16, 256>>>(W3, W4, gamma);
    gemm_relu<<<GRID_BLOCKS, BLOCK_THREADS>>>(x, out, ntiles);
}